// round 5
// baseline (speedup 1.0000x reference)
#include <cuda_runtime.h>
#include <cuda_bf16.h>
#include <stdint.h>

#define NE 8
#define DD 1024
#define RR 64
#define TT 128
#define MAXN 16384
#define S1 104          // fc1 smem stride in bf16 (96 data + 8 pad)
#define S2 200          // fc2 smem stride in bf16 (192 data + 8 pad)

// ------------------------- device scratch ----------------------------------
__device__ int   g_counts[NE];
__device__ int   g_tok[NE * MAXN];
__device__ float g_gate[NE * MAXN];
__device__ float g_scratch[2u * MAXN * DD];                 // 128 MB
__device__ __align__(16) unsigned short g_xp[(size_t)MAXN * 3072];   // 96 MB  A-packed x
__device__ __align__(16) unsigned short g_w1p[NE * RR * 3072];       // 3 MB   B-packed W1
__device__ __align__(16) unsigned short g_w2p[NE * DD * 192];        // 3 MB   B-packed W2

// ------------------------- helpers -----------------------------------------
__device__ __forceinline__ uint32_t smem_u32(const void* p) {
    uint32_t a;
    asm("{ .reg .u64 t; cvta.to.shared.u64 t, %1; cvt.u32.u64 %0, t; }"
        : "=r"(a) : "l"(p));
    return a;
}
__device__ __forceinline__ void ldsm4(uint32_t* r, uint32_t addr) {
    asm volatile("ldmatrix.sync.aligned.m8n8.x4.shared.b16 {%0,%1,%2,%3}, [%4];"
                 : "=r"(r[0]), "=r"(r[1]), "=r"(r[2]), "=r"(r[3]) : "r"(addr));
}
__device__ __forceinline__ void mma16816(float* c, const uint32_t* a,
                                         const uint32_t* b) {
    asm volatile("mma.sync.aligned.m16n8k16.row.col.f32.bf16.bf16.f32 "
                 "{%0,%1,%2,%3}, {%4,%5,%6,%7}, {%8,%9}, {%0,%1,%2,%3};"
                 : "+f"(c[0]), "+f"(c[1]), "+f"(c[2]), "+f"(c[3])
                 : "r"(a[0]), "r"(a[1]), "r"(a[2]), "r"(a[3]),
                   "r"(b[0]), "r"(b[1]));
}
__device__ __forceinline__ void cp16(uint32_t d, const void* s) {
    asm volatile("cp.async.cg.shared.global [%0], [%1], 16;" :: "r"(d), "l"(s));
}
#define CP_COMMIT() asm volatile("cp.async.commit_group;" ::: "memory")
#define CP_WAIT1()  asm volatile("cp.async.wait_group 1;" ::: "memory")
#define CP_WAIT0()  asm volatile("cp.async.wait_group 0;" ::: "memory")

__device__ __forceinline__ void split2(float v, uint32_t& h, uint32_t& l) {
    __nv_bfloat16 hb = __float2bfloat16(v);
    h = (uint32_t)__bfloat16_as_ushort(hb);
    l = (uint32_t)__bfloat16_as_ushort(__float2bfloat16(v - __bfloat162float(hb)));
}
// A operand triple: per elem (h, l, h)
__device__ __forceinline__ void packA(float4 v, void* dst) {
    uint32_t h0,l0,h1,l1,h2,l2,h3,l3;
    split2(v.x,h0,l0); split2(v.y,h1,l1); split2(v.z,h2,l2); split2(v.w,h3,l3);
    uint2* d = (uint2*)dst;
    d[0] = make_uint2(h0 | (l0 << 16), h0 | (h1 << 16));
    d[1] = make_uint2(l1 | (h1 << 16), h2 | (l2 << 16));
    d[2] = make_uint2(h2 | (h3 << 16), l3 | (h3 << 16));
}
// B operand triple: per elem (h, h, l)
__device__ __forceinline__ void packB(float4 v, void* dst) {
    uint32_t h0,l0,h1,l1,h2,l2,h3,l3;
    split2(v.x,h0,l0); split2(v.y,h1,l1); split2(v.z,h2,l2); split2(v.w,h3,l3);
    uint2* d = (uint2*)dst;
    d[0] = make_uint2(h0 | (h0 << 16), l0 | (h1 << 16));
    d[1] = make_uint2(h1 | (l1 << 16), h2 | (h2 << 16));
    d[2] = make_uint2(l2 | (h3 << 16), h3 | (l3 << 16));
}

// ---------------------------------------------------------------------------
// pack_w: pre-split W1 / W2 into B-operand triple layout (once).
// ---------------------------------------------------------------------------
__global__ void pack_w_kernel(const float* __restrict__ W1,
                              const float* __restrict__ W2) {
    int idx = blockIdx.x * 256 + threadIdx.x;
    if (idx < NE * RR * 256) {                  // W1: 512 rows x 256 float4
        float4 v = ((const float4*)W1)[idx];
        packB(v, (char*)g_w1p + (size_t)(idx >> 8) * 6144 + (idx & 255) * 24);
    } else {
        idx -= NE * RR * 256;                   // W2: 8192 rows x 16 float4
        float4 v = ((const float4*)W2)[idx];
        packB(v, (char*)g_w2p + (size_t)(idx >> 4) * 384 + (idx & 15) * 24);
    }
}

// ---------------------------------------------------------------------------
// Fused router + x-pack: one pass over x computes logits AND writes the
// A-operand triple-split rows to g_xp. Block = 16 tokens, 8 passes of 2.
// ---------------------------------------------------------------------------
__global__ void __launch_bounds__(256)
router_pack_kernel(const float* __restrict__ x,
                   const float* __restrict__ Wg,
                   const float* __restrict__ bg, int N) {
    __shared__ float4 sWg[NE * 256];
    __shared__ float  sRed[8][16];
    int t = threadIdx.x, warp = t >> 5, lane = t & 31;
    const float4* Wg4 = (const float4*)Wg;
    for (int i = t; i < NE * 256; i += 256) sWg[i] = Wg4[i];
    __syncthreads();

    float4 wreg[NE];
#pragma unroll
    for (int e = 0; e < NE; e++) wreg[e] = sWg[e * 256 + t];

    for (int pass = 0; pass < 8; pass++) {
        int tok0 = blockIdx.x * 16 + pass * 2;
        float acc[2][NE];
#pragma unroll
        for (int i = 0; i < 2; i++)
#pragma unroll
            for (int e = 0; e < NE; e++) acc[i][e] = 0.f;
#pragma unroll
        for (int i = 0; i < 2; i++) {
            int tok = tok0 + i;
            if (tok < N) {
                float4 xv = ((const float4*)(x + (size_t)tok * DD))[t];
                packA(xv, (char*)g_xp + (size_t)tok * 6144 + t * 24);
#pragma unroll
                for (int e = 0; e < NE; e++) {
                    acc[i][e] = fmaf(xv.x, wreg[e].x, acc[i][e]);
                    acc[i][e] = fmaf(xv.y, wreg[e].y, acc[i][e]);
                    acc[i][e] = fmaf(xv.z, wreg[e].z, acc[i][e]);
                    acc[i][e] = fmaf(xv.w, wreg[e].w, acc[i][e]);
                }
            }
        }
#pragma unroll
        for (int i = 0; i < 2; i++)
#pragma unroll
            for (int e = 0; e < NE; e++) {
#pragma unroll
                for (int off = 16; off; off >>= 1)
                    acc[i][e] += __shfl_xor_sync(0xffffffffu, acc[i][e], off);
            }
        if (lane == 0) {
#pragma unroll
            for (int i = 0; i < 2; i++)
#pragma unroll
                for (int e = 0; e < NE; e++) sRed[warp][i * 8 + e] = acc[i][e];
        }
        __syncthreads();
        if (t < 16) {
            float v = sRed[0][t];
#pragma unroll
            for (int w = 1; w < 8; w++) v += sRed[w][t];
            sRed[0][t] = v;
        }
        __syncthreads();
        if (t < 2) {
            int tok = tok0 + t;
            if (tok < N) {
                float l[NE];
#pragma unroll
                for (int e = 0; e < NE; e++) l[e] = sRed[0][t * 8 + e] + bg[e];
                int i0 = 0;
#pragma unroll
                for (int e = 1; e < NE; e++) if (l[e] > l[i0]) i0 = e;
                int i1 = (i0 == 0) ? 1 : 0;
#pragma unroll
                for (int e = 0; e < NE; e++) if (e != i0 && l[e] > l[i1]) i1 = e;
                float ex = expf(l[i1] - l[i0]);
                float inv = 1.f / (1.f + ex);
                int p0 = atomicAdd(&g_counts[i0], 1);
                g_tok[i0 * MAXN + p0]  = tok * 2;
                g_gate[i0 * MAXN + p0] = inv;
                int p1 = atomicAdd(&g_counts[i1], 1);
                g_tok[i1 * MAXN + p1]  = tok * 2 + 1;
                g_gate[i1 * MAXN + p1] = ex * inv;
            }
        }
        __syncthreads();
    }
}

// ---------------------------------------------------------------------------
// Expert kernel: round-3 structure; staging now cp.async of PRE-PACKED data.
//   fc1: D1[128,64] = X3[128,3072] @ W1_3[64,3072]^T   (dbl-buf 2x39936)
//   epi: H3 -> smem at +102400
//   fc2: 8 chunks of 128 cols, W2 dbl-buf 2x51200.
// smem total 153600 B.
// ---------------------------------------------------------------------------
__global__ void __launch_bounds__(256, 1)
expert_kernel(const float* __restrict__ x,
              const float* __restrict__ W1,
              const float* __restrict__ W2) {
    extern __shared__ char dynsm[];
    __shared__ int   s_tok[TT];
    __shared__ float s_gate[TT];

    int e = blockIdx.x, tile = blockIdx.y;
    int cnt = g_counts[e];
    int base = tile * TT;
    if (base >= cnt) return;
    int nt = min(TT, cnt - base);

    int t = threadIdx.x, wid = t >> 5, l = t & 31;
    int wm = wid & 3, wn = wid >> 2;   // warp grid 4(M) x 2(N)

    if (t < TT) {
        if (t < nt) {
            s_tok[t]  = g_tok[e * MAXN + base + t];
            s_gate[t] = g_gate[e * MAXN + base + t];
        } else {
            s_tok[t]  = g_tok[e * MAXN + base];
            s_gate[t] = 0.f;
        }
    }
    __syncthreads();

    char* bufs = dynsm;
    char* Hs   = dynsm + 102400;
    const char* w1p_e = (const char*)g_w1p + (size_t)e * RR * 6144;
    const char* w2p_e = (const char*)g_w2p + (size_t)e * DD * 384;

    uint32_t a1_lo = (uint32_t)(((l & 7) + ((l >> 3) & 1) * 8) * S1 * 2 + (l >> 4) * 16);
    uint32_t b1_lo = (uint32_t)(((l & 7) + (l >> 4) * 8) * S1 * 2 + ((l >> 3) & 1) * 16);
    uint32_t a2_lo = (uint32_t)(((l & 7) + ((l >> 3) & 1) * 8) * S2 * 2 + (l >> 4) * 16);
    uint32_t b2_lo = (uint32_t)(((l & 7) + (l >> 4) * 8) * S2 * 2 + ((l >> 3) & 1) * 16);
    uint32_t bufs_a = smem_u32(bufs);

    // per-thread fixed copy roles
    int ar = t >> 1, ah = t & 1;                     // A: row, half (96B each)
    const char* aRow = (const char*)g_xp + (size_t)(s_tok[ar] >> 1) * 6144 + ah * 96;
    uint32_t aDst = bufs_a + ar * 208 + ah * 96;
    int br = t >> 2, bh = t & 3;                     // B1: row, 48B quarter
    const char* bRow = w1p_e + (size_t)br * 6144 + bh * 48;
    uint32_t bDst = bufs_a + 26624 + br * 208 + bh * 48;
    uint32_t wDst = bufs_a + ar * 400 + ah * 192;    // W2: row, half (192B each)

    auto stage1 = [&](int c, int buf) {
        uint32_t bo = buf * 39936;
        const char* sa = aRow + c * 192;
#pragma unroll
        for (int j = 0; j < 6; j++) cp16(aDst + bo + j * 16, sa + j * 16);
        const char* sb = bRow + c * 192;
#pragma unroll
        for (int j = 0; j < 3; j++) cp16(bDst + bo + j * 16, sb + j * 16);
        CP_COMMIT();
    };
    auto stage2 = [&](int n, int buf) {
        uint32_t bo = buf * 51200;
        const char* sw = w2p_e + (size_t)(n * TT + ar) * 384 + ah * 192;
#pragma unroll
        for (int j = 0; j < 12; j++) cp16(wDst + bo + j * 16, sw + j * 16);
        CP_COMMIT();
    };

    // ================= fc1 =================
    float acc[2][4][4];
#pragma unroll
    for (int i = 0; i < 2; i++)
#pragma unroll
        for (int j = 0; j < 4; j++)
#pragma unroll
            for (int k = 0; k < 4; k++) acc[i][j][k] = 0.f;

    stage1(0, 0);
    for (int c = 0; c < 32; c++) {
        int buf = c & 1;
        if (c + 1 < 32) { stage1(c + 1, (c + 1) & 1); CP_WAIT1(); }
        else            { CP_WAIT0(); }
        __syncthreads();
        uint32_t Aaddr = bufs_a + buf * 39936;
        uint32_t Baddr = Aaddr + 26624;
#pragma unroll
        for (int kk = 0; kk < 6; kk++) {
            uint32_t a[2][4], b[2][4];
#pragma unroll
            for (int mt = 0; mt < 2; mt++)
                ldsm4(a[mt], Aaddr + (wm * 32 + mt * 16) * S1 * 2 + kk * 32 + a1_lo);
#pragma unroll
            for (int pr = 0; pr < 2; pr++)
                ldsm4(b[pr], Baddr + (wn * 32 + pr * 16) * S1 * 2 + kk * 32 + b1_lo);
#pragma unroll
            for (int mt = 0; mt < 2; mt++)
#pragma unroll
                for (int ntl = 0; ntl < 4; ntl++)
                    mma16816(acc[mt][ntl], a[mt], &b[ntl >> 1][(ntl & 1) * 2]);
        }
        __syncthreads();
    }

    // prefetch fc2 chunk 0 while doing the epilogue
    stage2(0, 0);

    // ============ epilogue: gelu*gate*2 -> triple-split H in smem ===========
#pragma unroll
    for (int mt = 0; mt < 2; mt++) {
#pragma unroll
        for (int ntl = 0; ntl < 4; ntl++) {
#pragma unroll
            for (int half = 0; half < 2; half++) {
                int r = wm * 32 + mt * 16 + half * 8 + (l >> 2);
                float gs = s_gate[r] * 2.0f;   // SCALING = 128/64
                float v0 = acc[mt][ntl][half * 2 + 0];
                float v1 = acc[mt][ntl][half * 2 + 1];
                float g0 = 0.5f * v0 * (1.f + erff(v0 * 0.70710678118654752f)) * gs;
                float g1 = 0.5f * v1 * (1.f + erff(v1 * 0.70710678118654752f)) * gs;
                int n = wn * 32 + ntl * 8 + (l & 3) * 2;
                uint32_t h0, l0, h1, l1;
                split2(g0, h0, l0); split2(g1, h1, l1);
                uint32_t* d = (uint32_t*)(Hs + r * S2 * 2 + n * 6);
                d[0] = h0 | (l0 << 16);
                d[1] = h0 | (h1 << 16);
                d[2] = l1 | (h1 << 16);
            }
        }
    }
    __syncthreads();

    // ================= fc2: 8 chunks of 128 output cols =================
    uint32_t HsA = smem_u32(Hs);
    for (int n = 0; n < 8; n++) {
        int buf = n & 1;
        if (n + 1 < 8) { stage2(n + 1, (n + 1) & 1); CP_WAIT1(); }
        else           { CP_WAIT0(); }
        __syncthreads();
        float acc2[2][8][4];
#pragma unroll
        for (int i = 0; i < 2; i++)
#pragma unroll
            for (int j = 0; j < 8; j++)
#pragma unroll
                for (int k = 0; k < 4; k++) acc2[i][j][k] = 0.f;

        uint32_t Waddr = bufs_a + buf * 51200;
#pragma unroll
        for (int kk = 0; kk < 12; kk++) {
            uint32_t a[2][4], b[4][4];
#pragma unroll
            for (int mt = 0; mt < 2; mt++)
                ldsm4(a[mt], HsA + (wm * 32 + mt * 16) * S2 * 2 + kk * 32 + a2_lo);
#pragma unroll
            for (int pr = 0; pr < 4; pr++)
                ldsm4(b[pr], Waddr + (wn * 64 + pr * 16) * S2 * 2 + kk * 32 + b2_lo);
#pragma unroll
            for (int mt = 0; mt < 2; mt++)
#pragma unroll
                for (int ntl = 0; ntl < 8; ntl++)
                    mma16816(acc2[mt][ntl], a[mt], &b[ntl >> 1][(ntl & 1) * 2]);
        }
        // store to scratch
#pragma unroll
        for (int mt = 0; mt < 2; mt++) {
#pragma unroll
            for (int half = 0; half < 2; half++) {
                int r = wm * 32 + mt * 16 + half * 8 + (l >> 2);
                if (r < nt) {
                    int slot = s_tok[r];
                    float* dst = g_scratch + (size_t)slot * DD + n * 128
                               + wn * 64 + (l & 3) * 2;
#pragma unroll
                    for (int ntl = 0; ntl < 8; ntl++)
                        *(float2*)(dst + ntl * 8) =
                            make_float2(acc2[mt][ntl][half * 2 + 0],
                                        acc2[mt][ntl][half * 2 + 1]);
                }
            }
        }
        __syncthreads();
    }
}

// ---------------------------------------------------------------------------
__global__ void combine_kernel(float* __restrict__ out, int N) {
    int i = blockIdx.x * blockDim.x + threadIdx.x;
    int total = N * (DD / 4);
    if (i >= total) return;
    int tok = i >> 8;
    int dd  = i & 255;
    const float4* s = (const float4*)g_scratch;
    float4 a = s[(size_t)tok * 512 + dd];
    float4 b = s[(size_t)tok * 512 + 256 + dd];
    float4 o;
    o.x = a.x + b.x; o.y = a.y + b.y; o.z = a.z + b.z; o.w = a.w + b.w;
    ((float4*)out)[i] = o;
}

// ---------------------------------------------------------------------------
extern "C" void kernel_launch(void* const* d_in, const int* in_sizes, int n_in,
                              void* d_out, int out_size) {
    const float* x  = (const float*)d_in[0];
    const float* Wg = (const float*)d_in[1];
    const float* bg = (const float*)d_in[2];
    const float* W1 = (const float*)d_in[3];
    const float* W2 = (const float*)d_in[4];
    float* out = (float*)d_out;
    int N = in_sizes[0] / DD;

    cudaFuncSetAttribute(expert_kernel,
                         cudaFuncAttributeMaxDynamicSharedMemorySize, 153600);

    void* counts_ptr = nullptr;
    cudaGetSymbolAddress(&counts_ptr, g_counts);
    cudaMemsetAsync(counts_ptr, 0, NE * sizeof(int), 0);

    pack_w_kernel<<<(NE * RR * 256 + NE * DD * 16 + 255) / 256, 256>>>(W1, W2);
    router_pack_kernel<<<(N + 15) / 16, 256>>>(x, Wg, bg, N);

    dim3 egrid(NE, 128);
    expert_kernel<<<egrid, 256, 153600>>>(x, W1, W2);

    int total = N * (DD / 4);
    combine_kernel<<<(total + 255) / 256, 256>>>(out, N);
}

// round 7
// speedup vs baseline: 1.0934x; 1.0934x over previous
#include <cuda_runtime.h>
#include <cuda_bf16.h>
#include <stdint.h>

#define NE 8
#define DD 1024
#define RR 64
#define TT 128
#define MAXN 16384
#define S1 104          // fc1 smem stride in bf16 (96 data + 8 pad)
#define S2 200          // fc2 smem stride in bf16 (192 data + 8 pad)

// ------------------------- device scratch ----------------------------------
__device__ int   g_counts[NE];
__device__ int   g_tok[NE * MAXN];
__device__ float g_gate[NE * MAXN];
__device__ float g_scratch[2u * MAXN * DD];                    // 128 MB
__device__ __align__(16) unsigned short g_w1p[NE * RR * 3072]; // 3 MB packed W1
__device__ __align__(16) unsigned short g_w2p[NE * DD * 192];  // 3 MB packed W2

// ------------------------- helpers -----------------------------------------
__device__ __forceinline__ uint32_t smem_u32(const void* p) {
    uint32_t a;
    asm("{ .reg .u64 t; cvta.to.shared.u64 t, %1; cvt.u32.u64 %0, t; }"
        : "=r"(a) : "l"(p));
    return a;
}
__device__ __forceinline__ void ldsm4(uint32_t* r, uint32_t addr) {
    asm volatile("ldmatrix.sync.aligned.m8n8.x4.shared.b16 {%0,%1,%2,%3}, [%4];"
                 : "=r"(r[0]), "=r"(r[1]), "=r"(r[2]), "=r"(r[3]) : "r"(addr));
}
__device__ __forceinline__ void mma16816(float* c, const uint32_t* a,
                                         const uint32_t* b) {
    asm volatile("mma.sync.aligned.m16n8k16.row.col.f32.bf16.bf16.f32 "
                 "{%0,%1,%2,%3}, {%4,%5,%6,%7}, {%8,%9}, {%0,%1,%2,%3};"
                 : "+f"(c[0]), "+f"(c[1]), "+f"(c[2]), "+f"(c[3])
                 : "r"(a[0]), "r"(a[1]), "r"(a[2]), "r"(a[3]),
                   "r"(b[0]), "r"(b[1]));
}
__device__ __forceinline__ void cp16(uint32_t d, const void* s) {
    asm volatile("cp.async.cg.shared.global [%0], [%1], 16;" :: "r"(d), "l"(s));
}
#define CP_COMMIT() asm volatile("cp.async.commit_group;" ::: "memory")
#define CP_WAIT0()  asm volatile("cp.async.wait_group 0;" ::: "memory")

__device__ __forceinline__ void split2(float v, uint32_t& h, uint32_t& l) {
    __nv_bfloat16 hb = __float2bfloat16(v);
    h = (uint32_t)__bfloat16_as_ushort(hb);
    l = (uint32_t)__bfloat16_as_ushort(__float2bfloat16(v - __bfloat162float(hb)));
}
// A operand triple: per elem (h, l, h)
__device__ __forceinline__ void packA(float4 v, void* dst) {
    uint32_t h0,l0,h1,l1,h2,l2,h3,l3;
    split2(v.x,h0,l0); split2(v.y,h1,l1); split2(v.z,h2,l2); split2(v.w,h3,l3);
    uint2* d = (uint2*)dst;
    d[0] = make_uint2(h0 | (l0 << 16), h0 | (h1 << 16));
    d[1] = make_uint2(l1 | (h1 << 16), h2 | (l2 << 16));
    d[2] = make_uint2(h2 | (h3 << 16), l3 | (h3 << 16));
}
// B operand triple: per elem (h, h, l)
__device__ __forceinline__ void packB(float4 v, void* dst) {
    uint32_t h0,l0,h1,l1,h2,l2,h3,l3;
    split2(v.x,h0,l0); split2(v.y,h1,l1); split2(v.z,h2,l2); split2(v.w,h3,l3);
    uint2* d = (uint2*)dst;
    d[0] = make_uint2(h0 | (h0 << 16), l0 | (h1 << 16));
    d[1] = make_uint2(h1 | (l1 << 16), h2 | (h2 << 16));
    d[2] = make_uint2(l2 | (h3 << 16), h3 | (l3 << 16));
}

// ---------------------------------------------------------------------------
// pack_w: pre-split W1 / W2 into B-operand triple layout (tiny, runs once).
// ---------------------------------------------------------------------------
__global__ void pack_w_kernel(const float* __restrict__ W1,
                              const float* __restrict__ W2) {
    int idx = blockIdx.x * 256 + threadIdx.x;
    if (idx < NE * RR * 256) {                  // W1: 512 rows x 256 float4
        float4 v = ((const float4*)W1)[idx];
        packB(v, (char*)g_w1p + (size_t)(idx >> 8) * 6144 + (idx & 255) * 24);
    } else {
        idx -= NE * RR * 256;                   // W2: 8192 rows x 16 float4
        float4 v = ((const float4*)W2)[idx];
        packB(v, (char*)g_w2p + (size_t)(idx >> 4) * 384 + (idx & 15) * 24);
    }
}

// ---------------------------------------------------------------------------
// Router: Wg cached in REGISTERS (each thread owns its float4 slice of all
// 8 expert rows). Block reduces 2 tokens/pass via shuffle + smem.
// ---------------------------------------------------------------------------
__global__ void __launch_bounds__(256)
router_kernel(const float* __restrict__ x,
              const float* __restrict__ Wg,
              const float* __restrict__ bg, int N) {
    __shared__ float sRed[8][16];
    int t = threadIdx.x, warp = t >> 5, lane = t & 31;

    float4 wreg[NE];
#pragma unroll
    for (int e = 0; e < NE; e++) wreg[e] = ((const float4*)Wg)[e * 256 + t];

    for (int pass = 0; pass < 8; pass++) {
        int tok0 = blockIdx.x * 16 + pass * 2;
        float acc[2][NE];
#pragma unroll
        for (int i = 0; i < 2; i++)
#pragma unroll
            for (int e = 0; e < NE; e++) acc[i][e] = 0.f;
#pragma unroll
        for (int i = 0; i < 2; i++) {
            int tok = tok0 + i;
            if (tok < N) {
                float4 xv = ((const float4*)(x + (size_t)tok * DD))[t];
#pragma unroll
                for (int e = 0; e < NE; e++) {
                    acc[i][e] = fmaf(xv.x, wreg[e].x, acc[i][e]);
                    acc[i][e] = fmaf(xv.y, wreg[e].y, acc[i][e]);
                    acc[i][e] = fmaf(xv.z, wreg[e].z, acc[i][e]);
                    acc[i][e] = fmaf(xv.w, wreg[e].w, acc[i][e]);
                }
            }
        }
#pragma unroll
        for (int i = 0; i < 2; i++)
#pragma unroll
            for (int e = 0; e < NE; e++) {
#pragma unroll
                for (int off = 16; off; off >>= 1)
                    acc[i][e] += __shfl_xor_sync(0xffffffffu, acc[i][e], off);
            }
        if (lane == 0) {
#pragma unroll
            for (int i = 0; i < 2; i++)
#pragma unroll
                for (int e = 0; e < NE; e++) sRed[warp][i * 8 + e] = acc[i][e];
        }
        __syncthreads();
        if (t < 16) {
            float v = sRed[0][t];
#pragma unroll
            for (int w = 1; w < 8; w++) v += sRed[w][t];
            sRed[0][t] = v;
        }
        __syncthreads();
        if (t < 2) {
            int tok = tok0 + t;
            if (tok < N) {
                float l[NE];
#pragma unroll
                for (int e = 0; e < NE; e++) l[e] = sRed[0][t * 8 + e] + bg[e];
                int i0 = 0;
#pragma unroll
                for (int e = 1; e < NE; e++) if (l[e] > l[i0]) i0 = e;
                int i1 = (i0 == 0) ? 1 : 0;
#pragma unroll
                for (int e = 0; e < NE; e++) if (e != i0 && l[e] > l[i1]) i1 = e;
                float ex = expf(l[i1] - l[i0]);
                float inv = 1.f / (1.f + ex);
                int p0 = atomicAdd(&g_counts[i0], 1);
                g_tok[i0 * MAXN + p0]  = tok * 2;
                g_gate[i0 * MAXN + p0] = inv;
                int p1 = atomicAdd(&g_counts[i1], 1);
                g_tok[i1 * MAXN + p1]  = tok * 2 + 1;
                g_gate[i1 * MAXN + p1] = ex * inv;
            }
        }
        __syncthreads();
    }
}

// ---------------------------------------------------------------------------
// Expert kernel (round-3 structure): X packed in-kernel; W tiles cp.async'd
// from pre-packed g_w1p/g_w2p.
//   fc1: D1[128,64] = X3[128,3072] @ W1_3[64,3072]^T   (dbl-buf 2x39936)
//   epi: H3 -> smem at +102400
//   fc2: 8 chunks of 128 cols, W2 dbl-buf 2x51200.
// ---------------------------------------------------------------------------
__global__ void __launch_bounds__(256, 1)
expert_kernel(const float* __restrict__ x,
              const float* __restrict__ W1,
              const float* __restrict__ W2) {
    extern __shared__ char dynsm[];
    __shared__ int   s_tok[TT];
    __shared__ float s_gate[TT];

    int e = blockIdx.x, tile = blockIdx.y;
    int cnt = g_counts[e];
    int base = tile * TT;
    if (base >= cnt) return;
    int nt = min(TT, cnt - base);

    int t = threadIdx.x, wid = t >> 5, l = t & 31;
    int wm = wid & 3, wn = wid >> 2;   // warp grid 4(M) x 2(N)

    if (t < TT) {
        if (t < nt) {
            s_tok[t]  = g_tok[e * MAXN + base + t];
            s_gate[t] = g_gate[e * MAXN + base + t];
        } else {
            s_tok[t]  = g_tok[e * MAXN + base];
            s_gate[t] = 0.f;
        }
    }
    __syncthreads();

    char* bufs = dynsm;
    char* Hs   = dynsm + 102400;
    const char* w1p_e = (const char*)g_w1p + (size_t)e * RR * 6144;
    const char* w2p_e = (const char*)g_w2p + (size_t)e * DD * 384;

    uint32_t a1_lo = (uint32_t)(((l & 7) + ((l >> 3) & 1) * 8) * S1 * 2 + (l >> 4) * 16);
    uint32_t b1_lo = (uint32_t)(((l & 7) + (l >> 4) * 8) * S1 * 2 + ((l >> 3) & 1) * 16);
    uint32_t a2_lo = (uint32_t)(((l & 7) + ((l >> 3) & 1) * 8) * S2 * 2 + (l >> 4) * 16);
    uint32_t b2_lo = (uint32_t)(((l & 7) + (l >> 4) * 8) * S2 * 2 + ((l >> 3) & 1) * 16);
    uint32_t bufs_a = smem_u32(bufs);

    // cp.async roles
    int br = t >> 2, bh = t & 3;       // B1: 64 rows, 48B quarter each
    const char* bRow = w1p_e + (size_t)br * 6144 + bh * 48;
    uint32_t bDst = bufs_a + 26624 + br * 208 + bh * 48;
    int wr = t >> 1, wh = t & 1;       // W2: 128 rows, 192B half each
    uint32_t wDst = bufs_a + wr * 400 + wh * 192;

    auto stageB1 = [&](int c, int buf) {
        uint32_t bo = buf * 39936;
        const char* sb = bRow + c * 192;
#pragma unroll
        for (int j = 0; j < 3; j++) cp16(bDst + bo + j * 16, sb + j * 16);
        CP_COMMIT();
    };
    auto stageW2 = [&](int n, int buf) {
        uint32_t bo = buf * 51200;
        const char* sw = w2p_e + (size_t)(n * TT + wr) * 384 + wh * 192;
#pragma unroll
        for (int j = 0; j < 12; j++) cp16(wDst + bo + j * 16, sw + j * 16);
        CP_COMMIT();
    };

    // ================= fc1 =================
    float acc[2][4][4];
#pragma unroll
    for (int i = 0; i < 2; i++)
#pragma unroll
        for (int j = 0; j < 4; j++)
#pragma unroll
            for (int k = 0; k < 4; k++) acc[i][j][k] = 0.f;

    float4 pa[4];
    int arow = t >> 3, acol4 = t & 7;

    auto ldg1 = [&](int c) {
#pragma unroll
        for (int j = 0; j < 4; j++) {
            int r = arow + j * 32;
            int tok = s_tok[r] >> 1;
            pa[j] = *(const float4*)(x + (size_t)tok * DD + c * 32 + acol4 * 4);
        }
    };
    auto sts1 = [&](int buf) {
        char* As = bufs + buf * 39936;
#pragma unroll
        for (int j = 0; j < 4; j++) {
            int r = arow + j * 32;
            packA(pa[j], As + r * S1 * 2 + acol4 * 24);
        }
    };

    ldg1(0); stageB1(0, 0); sts1(0);
    CP_WAIT0();
    __syncthreads();

    for (int c = 0; c < 32; c++) {
        int buf = c & 1;
        if (c + 1 < 32) { ldg1(c + 1); stageB1(c + 1, buf ^ 1); }
        uint32_t Aaddr = bufs_a + buf * 39936;
        uint32_t Baddr = Aaddr + 26624;
#pragma unroll
        for (int kk = 0; kk < 6; kk++) {
            uint32_t a[2][4], b[2][4];
#pragma unroll
            for (int mt = 0; mt < 2; mt++)
                ldsm4(a[mt], Aaddr + (wm * 32 + mt * 16) * S1 * 2 + kk * 32 + a1_lo);
#pragma unroll
            for (int pr = 0; pr < 2; pr++)
                ldsm4(b[pr], Baddr + (wn * 32 + pr * 16) * S1 * 2 + kk * 32 + b1_lo);
#pragma unroll
            for (int mt = 0; mt < 2; mt++)
#pragma unroll
                for (int ntl = 0; ntl < 4; ntl++)
                    mma16816(acc[mt][ntl], a[mt], &b[ntl >> 1][(ntl & 1) * 2]);
        }
        if (c + 1 < 32) sts1(buf ^ 1);
        CP_WAIT0();
        __syncthreads();
    }

    // prefetch fc2 chunk 0 while doing the epilogue
    stageW2(0, 0);

    // ============ epilogue: gelu*gate*2 -> triple-split H in smem ===========
#pragma unroll
    for (int mt = 0; mt < 2; mt++) {
#pragma unroll
        for (int ntl = 0; ntl < 4; ntl++) {
#pragma unroll
            for (int half = 0; half < 2; half++) {
                int r = wm * 32 + mt * 16 + half * 8 + (l >> 2);
                float gs = s_gate[r] * 2.0f;   // SCALING = 128/64
                float v0 = acc[mt][ntl][half * 2 + 0];
                float v1 = acc[mt][ntl][half * 2 + 1];
                float g0 = 0.5f * v0 * (1.f + erff(v0 * 0.70710678118654752f)) * gs;
                float g1 = 0.5f * v1 * (1.f + erff(v1 * 0.70710678118654752f)) * gs;
                int n = wn * 32 + ntl * 8 + (l & 3) * 2;
                uint32_t h0, l0, h1, l1;
                split2(g0, h0, l0); split2(g1, h1, l1);
                uint32_t* d = (uint32_t*)(Hs + r * S2 * 2 + n * 6);
                d[0] = h0 | (l0 << 16);
                d[1] = h0 | (h1 << 16);
                d[2] = l1 | (h1 << 16);
            }
        }
    }
    CP_WAIT0();
    __syncthreads();

    // ================= fc2: 8 chunks of 128 output cols =================
    uint32_t HsA = smem_u32(Hs);
    for (int n = 0; n < 8; n++) {
        int buf = n & 1;
        if (n + 1 < 8) stageW2(n + 1, buf ^ 1);
        float acc2[2][8][4];
#pragma unroll
        for (int i = 0; i < 2; i++)
#pragma unroll
            for (int j = 0; j < 8; j++)
#pragma unroll
                for (int k = 0; k < 4; k++) acc2[i][j][k] = 0.f;

        uint32_t Waddr = bufs_a + buf * 51200;
#pragma unroll
        for (int kk = 0; kk < 12; kk++) {
            uint32_t a[2][4], b[4][4];
#pragma unroll
            for (int mt = 0; mt < 2; mt++)
                ldsm4(a[mt], HsA + (wm * 32 + mt * 16) * S2 * 2 + kk * 32 + a2_lo);
#pragma unroll
            for (int pr = 0; pr < 4; pr++)
                ldsm4(b[pr], Waddr + (wn * 64 + pr * 16) * S2 * 2 + kk * 32 + b2_lo);
#pragma unroll
            for (int mt = 0; mt < 2; mt++)
#pragma unroll
                for (int ntl = 0; ntl < 8; ntl++)
                    mma16816(acc2[mt][ntl], a[mt], &b[ntl >> 1][(ntl & 1) * 2]);
        }
        // store to scratch
#pragma unroll
        for (int mt = 0; mt < 2; mt++) {
#pragma unroll
            for (int half = 0; half < 2; half++) {
                int r = wm * 32 + mt * 16 + half * 8 + (l >> 2);
                if (r < nt) {
                    int slot = s_tok[r];
                    float* dst = g_scratch + (size_t)slot * DD + n * 128
                               + wn * 64 + (l & 3) * 2;
#pragma unroll
                    for (int ntl = 0; ntl < 8; ntl++)
                        *(float2*)(dst + ntl * 8) =
                            make_float2(acc2[mt][ntl][half * 2 + 0],
                                        acc2[mt][ntl][half * 2 + 1]);
                }
            }
        }
        CP_WAIT0();
        __syncthreads();
    }
}

// ---------------------------------------------------------------------------
__global__ void combine_kernel(float* __restrict__ out, int N) {
    int i = blockIdx.x * blockDim.x + threadIdx.x;
    int total = N * (DD / 4);
    if (i >= total) return;
    int tok = i >> 8;
    int dd  = i & 255;
    const float4* s = (const float4*)g_scratch;
    float4 a = s[(size_t)tok * 512 + dd];
    float4 b = s[(size_t)tok * 512 + 256 + dd];
    float4 o;
    o.x = a.x + b.x; o.y = a.y + b.y; o.z = a.z + b.z; o.w = a.w + b.w;
    ((float4*)out)[i] = o;
}

// ---------------------------------------------------------------------------
extern "C" void kernel_launch(void* const* d_in, const int* in_sizes, int n_in,
                              void* d_out, int out_size) {
    const float* x  = (const float*)d_in[0];
    const float* Wg = (const float*)d_in[1];
    const float* bg = (const float*)d_in[2];
    const float* W1 = (const float*)d_in[3];
    const float* W2 = (const float*)d_in[4];
    float* out = (float*)d_out;
    int N = in_sizes[0] / DD;

    cudaFuncSetAttribute(expert_kernel,
                         cudaFuncAttributeMaxDynamicSharedMemorySize, 153600);

    void* counts_ptr = nullptr;
    cudaGetSymbolAddress(&counts_ptr, g_counts);
    cudaMemsetAsync(counts_ptr, 0, NE * sizeof(int), 0);

    pack_w_kernel<<<(NE * RR * 256 + NE * DD * 16 + 255) / 256, 256>>>(W1, W2);
    router_kernel<<<(N + 15) / 16, 256>>>(x, Wg, bg, N);

    dim3 egrid(NE, 128);
    expert_kernel<<<egrid, 256, 153600>>>(x, W1, W2);

    int total = N * (DD / 4);
    combine_kernel<<<(total + 255) / 256, 256>>>(out, N);
}

// round 8
// speedup vs baseline: 1.2072x; 1.1040x over previous
#include <cuda_runtime.h>
#include <cuda_bf16.h>
#include <stdint.h>

#define NE 8
#define DD 1024
#define RR 64
#define TT 128
#define MAXN 16384
#define S1 104          // fc1 smem stride in bf16 (96 data + 8 pad)
#define S2 200          // fc2 smem stride in bf16 (192 data + 8 pad)

// ------------------------- device scratch ----------------------------------
__device__ int   g_counts[NE];
__device__ int   g_tok[NE * MAXN];          // encoded tok*2 + k
__device__ float g_gate[NE * MAXN];
__device__ float g_scratch[2u * MAXN * DD]; // 128 MB per-(token,k) contribution

// ------------------------- helpers -----------------------------------------
__device__ __forceinline__ uint32_t smem_u32(const void* p) {
    uint32_t a;
    asm("{ .reg .u64 t; cvta.to.shared.u64 t, %1; cvt.u32.u64 %0, t; }"
        : "=r"(a) : "l"(p));
    return a;
}
__device__ __forceinline__ void ldsm4(uint32_t* r, uint32_t addr) {
    asm volatile("ldmatrix.sync.aligned.m8n8.x4.shared.b16 {%0,%1,%2,%3}, [%4];"
                 : "=r"(r[0]), "=r"(r[1]), "=r"(r[2]), "=r"(r[3]) : "r"(addr));
}
__device__ __forceinline__ void mma16816(float* c, const uint32_t* a,
                                         const uint32_t* b) {
    asm volatile("mma.sync.aligned.m16n8k16.row.col.f32.bf16.bf16.f32 "
                 "{%0,%1,%2,%3}, {%4,%5,%6,%7}, {%8,%9}, {%0,%1,%2,%3};"
                 : "+f"(c[0]), "+f"(c[1]), "+f"(c[2]), "+f"(c[3])
                 : "r"(a[0]), "r"(a[1]), "r"(a[2]), "r"(a[3]),
                   "r"(b[0]), "r"(b[1]));
}
__device__ __forceinline__ void split2(float v, uint32_t& h, uint32_t& l) {
    __nv_bfloat16 hb = __float2bfloat16(v);
    h = (uint32_t)__bfloat16_as_ushort(hb);
    l = (uint32_t)__bfloat16_as_ushort(__float2bfloat16(v - __bfloat162float(hb)));
}
// A operand triple: per elem (h, l, h)
__device__ __forceinline__ void packA(float4 v, void* dst) {
    uint32_t h0,l0,h1,l1,h2,l2,h3,l3;
    split2(v.x,h0,l0); split2(v.y,h1,l1); split2(v.z,h2,l2); split2(v.w,h3,l3);
    uint2* d = (uint2*)dst;
    d[0] = make_uint2(h0 | (l0 << 16), h0 | (h1 << 16));
    d[1] = make_uint2(l1 | (h1 << 16), h2 | (l2 << 16));
    d[2] = make_uint2(h2 | (h3 << 16), l3 | (h3 << 16));
}
// B operand triple: per elem (h, h, l)
__device__ __forceinline__ void packB(float4 v, void* dst) {
    uint32_t h0,l0,h1,l1,h2,l2,h3,l3;
    split2(v.x,h0,l0); split2(v.y,h1,l1); split2(v.z,h2,l2); split2(v.w,h3,l3);
    uint2* d = (uint2*)dst;
    d[0] = make_uint2(h0 | (h0 << 16), l0 | (h1 << 16));
    d[1] = make_uint2(h1 | (l1 << 16), h2 | (h2 << 16));
    d[2] = make_uint2(l2 | (h3 << 16), h3 | (l3 << 16));
}

// ---------------------------------------------------------------------------
// Router: Wg cached in REGISTERS (each thread owns its float4 slice of all
// 8 expert rows). Block reduces 2 tokens/pass via shuffle + smem.
// ---------------------------------------------------------------------------
__global__ void __launch_bounds__(256)
router_kernel(const float* __restrict__ x,
              const float* __restrict__ Wg,
              const float* __restrict__ bg, int N) {
    __shared__ float sRed[8][16];
    int t = threadIdx.x, warp = t >> 5, lane = t & 31;

    float4 wreg[NE];
#pragma unroll
    for (int e = 0; e < NE; e++) wreg[e] = ((const float4*)Wg)[e * 256 + t];

    for (int pass = 0; pass < 8; pass++) {
        int tok0 = blockIdx.x * 16 + pass * 2;
        float acc[2][NE];
#pragma unroll
        for (int i = 0; i < 2; i++)
#pragma unroll
            for (int e = 0; e < NE; e++) acc[i][e] = 0.f;
#pragma unroll
        for (int i = 0; i < 2; i++) {
            int tok = tok0 + i;
            if (tok < N) {
                float4 xv = ((const float4*)(x + (size_t)tok * DD))[t];
#pragma unroll
                for (int e = 0; e < NE; e++) {
                    acc[i][e] = fmaf(xv.x, wreg[e].x, acc[i][e]);
                    acc[i][e] = fmaf(xv.y, wreg[e].y, acc[i][e]);
                    acc[i][e] = fmaf(xv.z, wreg[e].z, acc[i][e]);
                    acc[i][e] = fmaf(xv.w, wreg[e].w, acc[i][e]);
                }
            }
        }
#pragma unroll
        for (int i = 0; i < 2; i++)
#pragma unroll
            for (int e = 0; e < NE; e++) {
#pragma unroll
                for (int off = 16; off; off >>= 1)
                    acc[i][e] += __shfl_xor_sync(0xffffffffu, acc[i][e], off);
            }
        if (lane == 0) {
#pragma unroll
            for (int i = 0; i < 2; i++)
#pragma unroll
                for (int e = 0; e < NE; e++) sRed[warp][i * 8 + e] = acc[i][e];
        }
        __syncthreads();
        if (t < 16) {
            float v = sRed[0][t];
#pragma unroll
            for (int w = 1; w < 8; w++) v += sRed[w][t];
            sRed[0][t] = v;
        }
        __syncthreads();
        if (t < 2) {
            int tok = tok0 + t;
            if (tok < N) {
                float l[NE];
#pragma unroll
                for (int e = 0; e < NE; e++) l[e] = sRed[0][t * 8 + e] + bg[e];
                int i0 = 0;
#pragma unroll
                for (int e = 1; e < NE; e++) if (l[e] > l[i0]) i0 = e;
                int i1 = (i0 == 0) ? 1 : 0;
#pragma unroll
                for (int e = 0; e < NE; e++) if (e != i0 && l[e] > l[i1]) i1 = e;
                float ex = expf(l[i1] - l[i0]);
                float inv = 1.f / (1.f + ex);
                int p0 = atomicAdd(&g_counts[i0], 1);
                g_tok[i0 * MAXN + p0]  = tok * 2;
                g_gate[i0 * MAXN + p0] = inv;
                int p1 = atomicAdd(&g_counts[i1], 1);
                g_tok[i1 * MAXN + p1]  = tok * 2 + 1;
                g_gate[i1 * MAXN + p1] = ex * inv;
            }
        }
        __syncthreads();
    }
}

// ---------------------------------------------------------------------------
// Expert kernel: EXACT round-3 structure (measured 214us total build).
//   fc1: D1[128,64] = X3[128,3072] @ W1_3[64,3072]^T   (ldg->packA/packB->sts)
//   epi: H3 = triplesplit(gelu(D1)*gate*2) -> smem
//   fc2: 8 chunks of 128 cols, W2 dbl-buf.
// ---------------------------------------------------------------------------
__global__ void __launch_bounds__(256, 1)
expert_kernel(const float* __restrict__ x,
              const float* __restrict__ W1,
              const float* __restrict__ W2) {
    extern __shared__ char dynsm[];
    __shared__ int   s_tok[TT];
    __shared__ float s_gate[TT];

    int e = blockIdx.x, tile = blockIdx.y;
    int cnt = g_counts[e];
    int base = tile * TT;
    if (base >= cnt) return;
    int nt = min(TT, cnt - base);

    int t = threadIdx.x, wid = t >> 5, l = t & 31;
    int wm = wid & 3, wn = wid >> 2;   // warp grid 4(M) x 2(N)

    if (t < TT) {
        if (t < nt) {
            s_tok[t]  = g_tok[e * MAXN + base + t];
            s_gate[t] = g_gate[e * MAXN + base + t];
        } else {
            s_tok[t]  = g_tok[e * MAXN + base];
            s_gate[t] = 0.f;
        }
    }
    __syncthreads();

    char* bufs = dynsm;
    char* Hs   = dynsm + 102400;
    const float* W1e = W1 + (size_t)e * RR * DD;
    const float* W2e = W2 + (size_t)e * DD * RR;

    uint32_t a1_lo = (uint32_t)(((l & 7) + ((l >> 3) & 1) * 8) * S1 * 2 + (l >> 4) * 16);
    uint32_t b1_lo = (uint32_t)(((l & 7) + (l >> 4) * 8) * S1 * 2 + ((l >> 3) & 1) * 16);
    uint32_t a2_lo = (uint32_t)(((l & 7) + ((l >> 3) & 1) * 8) * S2 * 2 + (l >> 4) * 16);
    uint32_t b2_lo = (uint32_t)(((l & 7) + (l >> 4) * 8) * S2 * 2 + ((l >> 3) & 1) * 16);
    uint32_t bufs_a = smem_u32(bufs);

    // ================= fc1 =================
    float acc[2][4][4];
#pragma unroll
    for (int i = 0; i < 2; i++)
#pragma unroll
        for (int j = 0; j < 4; j++)
#pragma unroll
            for (int k = 0; k < 4; k++) acc[i][j][k] = 0.f;

    float4 pa[4], pb[2];
    int arow = t >> 3, acol4 = t & 7;

    auto ldg1 = [&](int c) {
#pragma unroll
        for (int j = 0; j < 4; j++) {
            int r = arow + j * 32;
            int tok = s_tok[r] >> 1;
            pa[j] = *(const float4*)(x + (size_t)tok * DD + c * 32 + acol4 * 4);
        }
#pragma unroll
        for (int j = 0; j < 2; j++) {
            int idx = t + j * 256;
            int r = idx >> 3, c4 = idx & 7;
            pb[j] = *(const float4*)(W1e + (size_t)r * DD + c * 32 + c4 * 4);
        }
    };
    auto sts1 = [&](int buf) {
        char* As = bufs + buf * 39936;
        char* Bs = As + 26624;
#pragma unroll
        for (int j = 0; j < 4; j++) {
            int r = arow + j * 32;
            packA(pa[j], As + r * S1 * 2 + acol4 * 24);
        }
#pragma unroll
        for (int j = 0; j < 2; j++) {
            int idx = t + j * 256;
            int r = idx >> 3, c4 = idx & 7;
            packB(pb[j], Bs + r * S1 * 2 + c4 * 24);
        }
    };

    ldg1(0); sts1(0);
    __syncthreads();

    for (int c = 0; c < 32; c++) {
        int buf = c & 1;
        if (c + 1 < 32) ldg1(c + 1);
        uint32_t Aaddr = bufs_a + buf * 39936;
        uint32_t Baddr = Aaddr + 26624;
#pragma unroll
        for (int kk = 0; kk < 6; kk++) {
            uint32_t a[2][4], b[2][4];
#pragma unroll
            for (int mt = 0; mt < 2; mt++)
                ldsm4(a[mt], Aaddr + (wm * 32 + mt * 16) * S1 * 2 + kk * 32 + a1_lo);
#pragma unroll
            for (int pr = 0; pr < 2; pr++)
                ldsm4(b[pr], Baddr + (wn * 32 + pr * 16) * S1 * 2 + kk * 32 + b1_lo);
#pragma unroll
            for (int mt = 0; mt < 2; mt++)
#pragma unroll
                for (int ntl = 0; ntl < 4; ntl++)
                    mma16816(acc[mt][ntl], a[mt], &b[ntl >> 1][(ntl & 1) * 2]);
        }
        if (c + 1 < 32) sts1((c + 1) & 1);
        __syncthreads();
    }

    // ============ epilogue: gelu*gate*2 -> triple-split H in smem ===========
#pragma unroll
    for (int mt = 0; mt < 2; mt++) {
#pragma unroll
        for (int ntl = 0; ntl < 4; ntl++) {
#pragma unroll
            for (int half = 0; half < 2; half++) {
                int r = wm * 32 + mt * 16 + half * 8 + (l >> 2);
                float gs = s_gate[r] * 2.0f;   // SCALING = 128/64
                float v0 = acc[mt][ntl][half * 2 + 0];
                float v1 = acc[mt][ntl][half * 2 + 1];
                float g0 = 0.5f * v0 * (1.f + erff(v0 * 0.70710678118654752f)) * gs;
                float g1 = 0.5f * v1 * (1.f + erff(v1 * 0.70710678118654752f)) * gs;
                int n = wn * 32 + ntl * 8 + (l & 3) * 2;
                uint32_t h0, l0, h1, l1;
                split2(g0, h0, l0); split2(g1, h1, l1);
                uint32_t* d = (uint32_t*)(Hs + r * S2 * 2 + n * 6);
                d[0] = h0 | (l0 << 16);
                d[1] = h0 | (h1 << 16);
                d[2] = l1 | (h1 << 16);
            }
        }
    }
    __syncthreads();

    // ================= fc2 =================
    uint32_t HsA = smem_u32(Hs);
    float4 pw[8];
    auto ldg2 = [&](int nch) {
#pragma unroll
        for (int j = 0; j < 8; j++) {
            int idx = t + j * 256;
            int r = idx >> 4, c4 = idx & 15;
            pw[j] = *(const float4*)(W2e + (size_t)(nch * TT + r) * RR + c4 * 4);
        }
    };
    auto sts2 = [&](int buf) {
        char* Ws = bufs + buf * 51200;
#pragma unroll
        for (int j = 0; j < 8; j++) {
            int idx = t + j * 256;
            int r = idx >> 4, c4 = idx & 15;
            packB(pw[j], Ws + r * S2 * 2 + c4 * 24);
        }
    };

    ldg2(0); sts2(0);
    __syncthreads();

    for (int n = 0; n < 8; n++) {
        int buf = n & 1;
        if (n + 1 < 8) ldg2(n + 1);
        float acc2[2][8][4];
#pragma unroll
        for (int i = 0; i < 2; i++)
#pragma unroll
            for (int j = 0; j < 8; j++)
#pragma unroll
                for (int k = 0; k < 4; k++) acc2[i][j][k] = 0.f;

        uint32_t Waddr = bufs_a + buf * 51200;
#pragma unroll
        for (int kk = 0; kk < 12; kk++) {
            uint32_t a[2][4], b[4][4];
#pragma unroll
            for (int mt = 0; mt < 2; mt++)
                ldsm4(a[mt], HsA + (wm * 32 + mt * 16) * S2 * 2 + kk * 32 + a2_lo);
#pragma unroll
            for (int pr = 0; pr < 4; pr++)
                ldsm4(b[pr], Waddr + (wn * 64 + pr * 16) * S2 * 2 + kk * 32 + b2_lo);
#pragma unroll
            for (int mt = 0; mt < 2; mt++)
#pragma unroll
                for (int ntl = 0; ntl < 8; ntl++)
                    mma16816(acc2[mt][ntl], a[mt], &b[ntl >> 1][(ntl & 1) * 2]);
        }
        // store to scratch
#pragma unroll
        for (int mt = 0; mt < 2; mt++) {
#pragma unroll
            for (int half = 0; half < 2; half++) {
                int r = wm * 32 + mt * 16 + half * 8 + (l >> 2);
                if (r < nt) {
                    int slot = s_tok[r];
                    float* dst = g_scratch + (size_t)slot * DD + n * 128
                               + wn * 64 + (l & 3) * 2;
#pragma unroll
                    for (int ntl = 0; ntl < 8; ntl++)
                        *(float2*)(dst + ntl * 8) =
                            make_float2(acc2[mt][ntl][half * 2 + 0],
                                        acc2[mt][ntl][half * 2 + 1]);
                }
            }
        }
        if (n + 1 < 8) sts2((n + 1) & 1);
        __syncthreads();
    }
}

// ---------------------------------------------------------------------------
__global__ void combine_kernel(float* __restrict__ out, int N) {
    int i = blockIdx.x * blockDim.x + threadIdx.x;
    int total = N * (DD / 4);
    if (i >= total) return;
    int tok = i >> 8;
    int dd  = i & 255;
    const float4* s = (const float4*)g_scratch;
    float4 a = s[(size_t)tok * 512 + dd];
    float4 b = s[(size_t)tok * 512 + 256 + dd];
    float4 o;
    o.x = a.x + b.x; o.y = a.y + b.y; o.z = a.z + b.z; o.w = a.w + b.w;
    ((float4*)out)[i] = o;
}

// ---------------------------------------------------------------------------
extern "C" void kernel_launch(void* const* d_in, const int* in_sizes, int n_in,
                              void* d_out, int out_size) {
    const float* x  = (const float*)d_in[0];
    const float* Wg = (const float*)d_in[1];
    const float* bg = (const float*)d_in[2];
    const float* W1 = (const float*)d_in[3];
    const float* W2 = (const float*)d_in[4];
    float* out = (float*)d_out;
    int N = in_sizes[0] / DD;

    cudaFuncSetAttribute(expert_kernel,
                         cudaFuncAttributeMaxDynamicSharedMemorySize, 153600);

    void* counts_ptr = nullptr;
    cudaGetSymbolAddress(&counts_ptr, g_counts);
    cudaMemsetAsync(counts_ptr, 0, NE * sizeof(int), 0);

    router_kernel<<<(N + 15) / 16, 256>>>(x, Wg, bg, N);

    dim3 egrid(NE, 128);
    expert_kernel<<<egrid, 256, 153600>>>(x, W1, W2);

    int total = N * (DD / 4);
    combine_kernel<<<(total + 255) / 256, 256>>>(out, N);
}

// round 9
// speedup vs baseline: 1.3543x; 1.1219x over previous
#include <cuda_runtime.h>
#include <cuda_bf16.h>
#include <stdint.h>

#define NE 8
#define DD 1024
#define RR 64
#define TT 128
#define MAXN 16384
#define S1 104          // fc1 smem stride in bf16 (96 data + 8 pad)
#define S2 200          // fc2 smem stride in bf16 (192 data + 8 pad)

// ------------------------- device scratch ----------------------------------
__device__ int   g_counts[NE];
__device__ int   g_tok[NE * MAXN];          // encoded tok*2 + k
__device__ float g_gate[NE * MAXN];
__device__ float g_scratch[2u * MAXN * DD]; // 128 MB per-(token,k) contribution

// ------------------------- helpers -----------------------------------------
__device__ __forceinline__ uint32_t smem_u32(const void* p) {
    uint32_t a;
    asm("{ .reg .u64 t; cvta.to.shared.u64 t, %1; cvt.u32.u64 %0, t; }"
        : "=r"(a) : "l"(p));
    return a;
}
__device__ __forceinline__ void ldsm4(uint32_t* r, uint32_t addr) {
    asm volatile("ldmatrix.sync.aligned.m8n8.x4.shared.b16 {%0,%1,%2,%3}, [%4];"
                 : "=r"(r[0]), "=r"(r[1]), "=r"(r[2]), "=r"(r[3]) : "r"(addr));
}
__device__ __forceinline__ void mma16816(float* c, const uint32_t* a,
                                         const uint32_t* b) {
    asm volatile("mma.sync.aligned.m16n8k16.row.col.f32.bf16.bf16.f32 "
                 "{%0,%1,%2,%3}, {%4,%5,%6,%7}, {%8,%9}, {%0,%1,%2,%3};"
                 : "+f"(c[0]), "+f"(c[1]), "+f"(c[2]), "+f"(c[3])
                 : "r"(a[0]), "r"(a[1]), "r"(a[2]), "r"(a[3]),
                   "r"(b[0]), "r"(b[1]));
}
__device__ __forceinline__ void split2(float v, uint32_t& h, uint32_t& l) {
    __nv_bfloat16 hb = __float2bfloat16(v);
    h = (uint32_t)__bfloat16_as_ushort(hb);
    l = (uint32_t)__bfloat16_as_ushort(__float2bfloat16(v - __bfloat162float(hb)));
}
// A operand triple: per elem (h, l, h)
__device__ __forceinline__ void packA(float4 v, void* dst) {
    uint32_t h0,l0,h1,l1,h2,l2,h3,l3;
    split2(v.x,h0,l0); split2(v.y,h1,l1); split2(v.z,h2,l2); split2(v.w,h3,l3);
    uint2* d = (uint2*)dst;
    d[0] = make_uint2(h0 | (l0 << 16), h0 | (h1 << 16));
    d[1] = make_uint2(l1 | (h1 << 16), h2 | (l2 << 16));
    d[2] = make_uint2(h2 | (h3 << 16), l3 | (h3 << 16));
}
// B operand triple: per elem (h, h, l)
__device__ __forceinline__ void packB(float4 v, void* dst) {
    uint32_t h0,l0,h1,l1,h2,l2,h3,l3;
    split2(v.x,h0,l0); split2(v.y,h1,l1); split2(v.z,h2,l2); split2(v.w,h3,l3);
    uint2* d = (uint2*)dst;
    d[0] = make_uint2(h0 | (h0 << 16), l0 | (h1 << 16));
    d[1] = make_uint2(h1 | (l1 << 16), h2 | (h2 << 16));
    d[2] = make_uint2(l2 | (h3 << 16), h3 | (l3 << 16));
}

// ---------------------------------------------------------------------------
// Router (verified 40us): warp per token, 4 tokens sequentially, float4 loads.
// ---------------------------------------------------------------------------
__global__ void router_kernel(const float* __restrict__ x,
                              const float* __restrict__ Wg,
                              const float* __restrict__ bg, int N) {
    __shared__ float4 sWg[NE * 256];
    int t = threadIdx.x;
    const float4* Wg4 = (const float4*)Wg;
    for (int i = t; i < NE * 256; i += 256) sWg[i] = Wg4[i];
    __syncthreads();

    int warp = t >> 5, lane = t & 31;
    for (int it = 0; it < 4; it++) {
        int tok = blockIdx.x * 32 + warp * 4 + it;
        if (tok >= N) break;
        const float4* xr = (const float4*)(x + (size_t)tok * DD);
        float acc[NE];
#pragma unroll
        for (int e = 0; e < NE; e++) acc[e] = 0.f;
#pragma unroll
        for (int i = 0; i < 8; i++) {
            float4 xv = xr[i * 32 + lane];
#pragma unroll
            for (int e = 0; e < NE; e++) {
                float4 w = sWg[e * 256 + i * 32 + lane];
                acc[e] = fmaf(xv.x, w.x, acc[e]);
                acc[e] = fmaf(xv.y, w.y, acc[e]);
                acc[e] = fmaf(xv.z, w.z, acc[e]);
                acc[e] = fmaf(xv.w, w.w, acc[e]);
            }
        }
#pragma unroll
        for (int e = 0; e < NE; e++) {
#pragma unroll
            for (int off = 16; off; off >>= 1)
                acc[e] += __shfl_xor_sync(0xffffffffu, acc[e], off);
        }
        if (lane == 0) {
            float l[NE];
#pragma unroll
            for (int e = 0; e < NE; e++) l[e] = acc[e] + bg[e];
            int i0 = 0;
#pragma unroll
            for (int e = 1; e < NE; e++) if (l[e] > l[i0]) i0 = e;
            int i1 = (i0 == 0) ? 1 : 0;
#pragma unroll
            for (int e = 0; e < NE; e++) if (e != i0 && l[e] > l[i1]) i1 = e;
            float ex = expf(l[i1] - l[i0]);
            float inv = 1.f / (1.f + ex);
            int p0 = atomicAdd(&g_counts[i0], 1);
            g_tok[i0 * MAXN + p0]  = tok * 2;
            g_gate[i0 * MAXN + p0] = inv;
            int p1 = atomicAdd(&g_counts[i1], 1);
            g_tok[i1 * MAXN + p1]  = tok * 2 + 1;
            g_gate[i1 * MAXN + p1] = ex * inv;
        }
    }
}

// ---------------------------------------------------------------------------
// Expert kernel: 512 threads (16 warps, 4M x 4N warp grid) for latency hiding.
// Same tiles/smem as the 214us build:
//   fc1: D1[128,64] = X3[128,3072] @ W1_3[64,3072]^T   (dbl-buf 2x39936)
//   epi: H3 -> smem at +102400
//   fc2: 8 chunks of 128 cols, W2 dbl-buf 2x51200.
// Warp tiles: fc1 32Mx16N, fc2 32Mx32N.
// ---------------------------------------------------------------------------
__global__ void __launch_bounds__(512, 1)
expert_kernel(const float* __restrict__ x,
              const float* __restrict__ W1,
              const float* __restrict__ W2) {
    extern __shared__ char dynsm[];
    __shared__ int   s_tok[TT];
    __shared__ float s_gate[TT];

    int e = blockIdx.x, tile = blockIdx.y;
    int cnt = g_counts[e];
    int base = tile * TT;
    if (base >= cnt) return;
    int nt = min(TT, cnt - base);

    int t = threadIdx.x, wid = t >> 5, l = t & 31;
    int wm = wid & 3, wn = wid >> 2;   // warp grid 4(M) x 4(N)

    if (t < TT) {
        if (t < nt) {
            s_tok[t]  = g_tok[e * MAXN + base + t];
            s_gate[t] = g_gate[e * MAXN + base + t];
        } else {
            s_tok[t]  = g_tok[e * MAXN + base];
            s_gate[t] = 0.f;
        }
    }
    __syncthreads();

    char* bufs = dynsm;
    char* Hs   = dynsm + 102400;
    const float* W1e = W1 + (size_t)e * RR * DD;
    const float* W2e = W2 + (size_t)e * DD * RR;

    uint32_t a1_lo = (uint32_t)(((l & 7) + ((l >> 3) & 1) * 8) * S1 * 2 + (l >> 4) * 16);
    uint32_t b1_lo = (uint32_t)(((l & 7) + (l >> 4) * 8) * S1 * 2 + ((l >> 3) & 1) * 16);
    uint32_t a2_lo = (uint32_t)(((l & 7) + ((l >> 3) & 1) * 8) * S2 * 2 + (l >> 4) * 16);
    uint32_t b2_lo = (uint32_t)(((l & 7) + (l >> 4) * 8) * S2 * 2 + ((l >> 3) & 1) * 16);
    uint32_t bufs_a = smem_u32(bufs);

    // ================= fc1 (warp tile 32M x 16N) =================
    float acc[2][2][4];
#pragma unroll
    for (int i = 0; i < 2; i++)
#pragma unroll
        for (int j = 0; j < 2; j++)
#pragma unroll
            for (int k = 0; k < 4; k++) acc[i][j][k] = 0.f;

    float4 pa[2], pb1;
    auto ldg1 = [&](int c) {
#pragma unroll
        for (int j = 0; j < 2; j++) {
            int idx = t + j * 512;
            int r = idx >> 3, c4 = idx & 7;
            int tok = s_tok[r] >> 1;
            pa[j] = *(const float4*)(x + (size_t)tok * DD + c * 32 + c4 * 4);
        }
        {
            int r = t >> 3, c4 = t & 7;        // 512 threads = 64 rows x 8 c4
            pb1 = *(const float4*)(W1e + (size_t)r * DD + c * 32 + c4 * 4);
        }
    };
    auto sts1 = [&](int buf) {
        char* As = bufs + buf * 39936;
        char* Bs = As + 26624;
#pragma unroll
        for (int j = 0; j < 2; j++) {
            int idx = t + j * 512;
            int r = idx >> 3, c4 = idx & 7;
            packA(pa[j], As + r * S1 * 2 + c4 * 24);
        }
        {
            int r = t >> 3, c4 = t & 7;
            packB(pb1, Bs + r * S1 * 2 + c4 * 24);
        }
    };

    ldg1(0); sts1(0);
    __syncthreads();

    for (int c = 0; c < 32; c++) {
        int buf = c & 1;
        if (c + 1 < 32) ldg1(c + 1);
        uint32_t Aaddr = bufs_a + buf * 39936;
        uint32_t Baddr = Aaddr + 26624;
#pragma unroll
        for (int kk = 0; kk < 6; kk++) {
            uint32_t a[2][4], b[4];
#pragma unroll
            for (int mt = 0; mt < 2; mt++)
                ldsm4(a[mt], Aaddr + (wm * 32 + mt * 16) * S1 * 2 + kk * 32 + a1_lo);
            ldsm4(b, Baddr + (wn * 16) * S1 * 2 + kk * 32 + b1_lo);
#pragma unroll
            for (int mt = 0; mt < 2; mt++)
#pragma unroll
                for (int ntl = 0; ntl < 2; ntl++)
                    mma16816(acc[mt][ntl], a[mt], &b[ntl * 2]);
        }
        if (c + 1 < 32) sts1((c + 1) & 1);
        __syncthreads();
    }

    // ============ epilogue: gelu*gate*2 -> triple-split H in smem ===========
#pragma unroll
    for (int mt = 0; mt < 2; mt++) {
#pragma unroll
        for (int ntl = 0; ntl < 2; ntl++) {
#pragma unroll
            for (int half = 0; half < 2; half++) {
                int r = wm * 32 + mt * 16 + half * 8 + (l >> 2);
                float gs = s_gate[r] * 2.0f;   // SCALING = 128/64
                float v0 = acc[mt][ntl][half * 2 + 0];
                float v1 = acc[mt][ntl][half * 2 + 1];
                float g0 = 0.5f * v0 * (1.f + erff(v0 * 0.70710678118654752f)) * gs;
                float g1 = 0.5f * v1 * (1.f + erff(v1 * 0.70710678118654752f)) * gs;
                int n = wn * 16 + ntl * 8 + (l & 3) * 2;
                uint32_t h0, l0, h1, l1;
                split2(g0, h0, l0); split2(g1, h1, l1);
                uint32_t* d = (uint32_t*)(Hs + r * S2 * 2 + n * 6);
                d[0] = h0 | (l0 << 16);
                d[1] = h0 | (h1 << 16);
                d[2] = l1 | (h1 << 16);
            }
        }
    }
    __syncthreads();

    // ================= fc2 (warp tile 32M x 32N) =================
    uint32_t HsA = smem_u32(Hs);
    float4 pw[4];
    auto ldg2 = [&](int nch) {
#pragma unroll
        for (int j = 0; j < 4; j++) {
            int idx = t + j * 512;
            int r = idx >> 4, c4 = idx & 15;
            pw[j] = *(const float4*)(W2e + (size_t)(nch * TT + r) * RR + c4 * 4);
        }
    };
    auto sts2 = [&](int buf) {
        char* Ws = bufs + buf * 51200;
#pragma unroll
        for (int j = 0; j < 4; j++) {
            int idx = t + j * 512;
            int r = idx >> 4, c4 = idx & 15;
            packB(pw[j], Ws + r * S2 * 2 + c4 * 24);
        }
    };

    ldg2(0); sts2(0);
    __syncthreads();

    for (int n = 0; n < 8; n++) {
        int buf = n & 1;
        if (n + 1 < 8) ldg2(n + 1);
        float acc2[2][4][4];
#pragma unroll
        for (int i = 0; i < 2; i++)
#pragma unroll
            for (int j = 0; j < 4; j++)
#pragma unroll
                for (int k = 0; k < 4; k++) acc2[i][j][k] = 0.f;

        uint32_t Waddr = bufs_a + buf * 51200;
#pragma unroll
        for (int kk = 0; kk < 12; kk++) {
            uint32_t a[2][4], b[2][4];
#pragma unroll
            for (int mt = 0; mt < 2; mt++)
                ldsm4(a[mt], HsA + (wm * 32 + mt * 16) * S2 * 2 + kk * 32 + a2_lo);
#pragma unroll
            for (int pr = 0; pr < 2; pr++)
                ldsm4(b[pr], Waddr + (wn * 32 + pr * 16) * S2 * 2 + kk * 32 + b2_lo);
#pragma unroll
            for (int mt = 0; mt < 2; mt++)
#pragma unroll
                for (int ntl = 0; ntl < 4; ntl++)
                    mma16816(acc2[mt][ntl], a[mt], &b[ntl >> 1][(ntl & 1) * 2]);
        }
        // store to scratch
#pragma unroll
        for (int mt = 0; mt < 2; mt++) {
#pragma unroll
            for (int half = 0; half < 2; half++) {
                int r = wm * 32 + mt * 16 + half * 8 + (l >> 2);
                if (r < nt) {
                    int slot = s_tok[r];
                    float* dst = g_scratch + (size_t)slot * DD + n * 128
                               + wn * 32 + (l & 3) * 2;
#pragma unroll
                    for (int ntl = 0; ntl < 4; ntl++)
                        *(float2*)(dst + ntl * 8) =
                            make_float2(acc2[mt][ntl][half * 2 + 0],
                                        acc2[mt][ntl][half * 2 + 1]);
                }
            }
        }
        if (n + 1 < 8) sts2((n + 1) & 1);
        __syncthreads();
    }
}

// ---------------------------------------------------------------------------
__global__ void combine_kernel(float* __restrict__ out, int N) {
    int i = blockIdx.x * blockDim.x + threadIdx.x;
    int total = N * (DD / 4);
    if (i >= total) return;
    int tok = i >> 8;
    int dd  = i & 255;
    const float4* s = (const float4*)g_scratch;
    float4 a = s[(size_t)tok * 512 + dd];
    float4 b = s[(size_t)tok * 512 + 256 + dd];
    float4 o;
    o.x = a.x + b.x; o.y = a.y + b.y; o.z = a.z + b.z; o.w = a.w + b.w;
    ((float4*)out)[i] = o;
}

// ---------------------------------------------------------------------------
extern "C" void kernel_launch(void* const* d_in, const int* in_sizes, int n_in,
                              void* d_out, int out_size) {
    const float* x  = (const float*)d_in[0];
    const float* Wg = (const float*)d_in[1];
    const float* bg = (const float*)d_in[2];
    const float* W1 = (const float*)d_in[3];
    const float* W2 = (const float*)d_in[4];
    float* out = (float*)d_out;
    int N = in_sizes[0] / DD;

    cudaFuncSetAttribute(expert_kernel,
                         cudaFuncAttributeMaxDynamicSharedMemorySize, 153600);

    void* counts_ptr = nullptr;
    cudaGetSymbolAddress(&counts_ptr, g_counts);
    cudaMemsetAsync(counts_ptr, 0, NE * sizeof(int), 0);

    router_kernel<<<(N + 31) / 32, 256>>>(x, Wg, bg, N);

    dim3 egrid(NE, 128);
    expert_kernel<<<egrid, 512, 153600>>>(x, W1, W2);

    int total = N * (DD / 4);
    combine_kernel<<<(total + 255) / 256, 256>>>(out, N);
}